// round 4
// baseline (speedup 1.0000x reference)
#include <cuda_runtime.h>
#include <cuda_bf16.h>

// Problem constants
constexpr int B_  = 2;
constexpr int L_  = 2048;
constexpr int D_  = 1024;
constexpr int H_  = 16;
constexpr int DK_ = 64;
constexpr int NT_ = B_ * L_;   // 4096 tokens
constexpr int BH_ = B_ * H_;   // 32

// --------------------------- device scratch --------------------------------
__device__ __nv_bfloat16 g_inHi[NT_ * D_];   // input / ctx split (reused)
__device__ __nv_bfloat16 g_inLo[NT_ * D_];
__device__ __nv_bfloat16 g_wHi[D_ * D_];     // weight split (reused per proj)
__device__ __nv_bfloat16 g_wLo[D_ * D_];
__device__ __nv_bfloat16 g_Qh[BH_ * L_ * DK_];
__device__ __nv_bfloat16 g_Ql[BH_ * L_ * DK_];
__device__ __nv_bfloat16 g_Kh[BH_ * L_ * DK_];
__device__ __nv_bfloat16 g_Kl[BH_ * L_ * DK_];
__device__ float g_V[BH_ * L_ * DK_];
__device__ float g_S[(size_t)BH_ * L_ * L_]; // 512 MB scores->probs in place

// --------------------------- bf16 split helpers ----------------------------
__device__ __forceinline__ void split2(float x, float y,
                                       __nv_bfloat162& hi, __nv_bfloat162& lo)
{
    hi = __floats2bfloat162_rn(x, y);
    float rx = x - __bfloat162float(hi.x);
    float ry = y - __bfloat162float(hi.y);
    lo = __floats2bfloat162_rn(rx, ry);
}

// Elementwise fp32 -> (hi, lo) bf16 split. n4 = element count / 4.
__global__ __launch_bounds__(256)
void split_kernel(const float* __restrict__ src,
                  __nv_bfloat16* __restrict__ hi,
                  __nv_bfloat16* __restrict__ lo, int n4)
{
    int i = blockIdx.x * 256 + threadIdx.x;
    if (i >= n4) return;
    float4 f = ((const float4*)src)[i];
    __nv_bfloat162 h01, l01, h23, l23;
    split2(f.x, f.y, h01, l01);
    split2(f.z, f.w, h23, l23);
    ((__nv_bfloat162*)hi)[2 * i]     = h01;
    ((__nv_bfloat162*)hi)[2 * i + 1] = h23;
    ((__nv_bfloat162*)lo)[2 * i]     = l01;
    ((__nv_bfloat162*)lo)[2 * i + 1] = l23;
}

// --------------------------- MMA primitive ---------------------------------
__device__ __forceinline__ void mma16816(float* c, const unsigned* a, const unsigned* b)
{
    asm volatile(
        "mma.sync.aligned.m16n8k16.row.col.f32.bf16.bf16.f32 "
        "{%0,%1,%2,%3}, {%4,%5,%6,%7}, {%8,%9}, {%0,%1,%2,%3};\n"
        : "+f"(c[0]), "+f"(c[1]), "+f"(c[2]), "+f"(c[3])
        : "r"(a[0]), "r"(a[1]), "r"(a[2]), "r"(a[3]), "r"(b[0]), "r"(b[1]));
}

// ---------------------------------------------------------------------------
// C = scale * A(MxK) @ W^T, A/W pre-split bf16 (k contiguous).
// Block 128x128, 256 thr (8 warps: wm 0-1 x 64 rows, wn 0-3 x 32 cols).
// Per warp: 4 m-tiles(16) x 4 n-tiles(8). 3-term bf16 split accumulation.
// mode 0: scatter hi/lo to g_Qh/g_Ql   (scale folded: 1/16)
// mode 1: scatter hi/lo to g_Kh/g_Kl
// mode 2: scatter fp32 to g_V
// mode 3: flat fp32 to Cout
// ---------------------------------------------------------------------------
__global__ __launch_bounds__(256, 1)
void mma_gemm_kernel(const __nv_bfloat16* __restrict__ Ah,
                     const __nv_bfloat16* __restrict__ Al,
                     const __nv_bfloat16* __restrict__ Wh,
                     const __nv_bfloat16* __restrict__ Wl,
                     float* __restrict__ Cout,
                     int M, int N, int K, float scale, int mode)
{
    __shared__ __nv_bfloat16 sAh[128 * 40];  // row stride 40 halves (80B): bank-clean
    __shared__ __nv_bfloat16 sAl[128 * 40];
    __shared__ __nv_bfloat16 sWh[128 * 40];
    __shared__ __nv_bfloat16 sWl[128 * 40];

    int tid = threadIdx.x;
    int warp = tid >> 5, lane = tid & 31;
    int wm = warp >> 2, wn = warp & 3;
    int g = lane >> 2, t = lane & 3;
    int m0 = blockIdx.y * 128;
    int n0 = blockIdx.x * 128;

    float acc[4][4][4] = {};

    for (int k0 = 0; k0 < K; k0 += 32) {
        // load: 512 float4 per array, 2 per thread per array
        #pragma unroll
        for (int i = 0; i < 2; i++) {
            int f = tid + i * 256;       // 0..511
            int r = f >> 2;              // 0..127
            int c8 = (f & 3) * 8;        // half offset in chunk
            size_t ga = (size_t)(m0 + r) * K + k0 + c8;
            size_t gw = (size_t)(n0 + r) * K + k0 + c8;
            *(float4*)&sAh[r * 40 + c8] = *(const float4*)&Ah[ga];
            *(float4*)&sAl[r * 40 + c8] = *(const float4*)&Al[ga];
            *(float4*)&sWh[r * 40 + c8] = *(const float4*)&Wh[gw];
            *(float4*)&sWl[r * 40 + c8] = *(const float4*)&Wl[gw];
        }
        __syncthreads();

        #pragma unroll
        for (int ks = 0; ks < 32; ks += 16) {
            unsigned ah[4][4], al[4][4], bh[4][2], bl[4][2];
            #pragma unroll
            for (int mi = 0; mi < 4; mi++) {
                int base = (wm * 64 + mi * 16 + g) * 40 + ks + 2 * t;
                ah[mi][0] = *(const unsigned*)&sAh[base];
                ah[mi][1] = *(const unsigned*)&sAh[base + 8 * 40];
                ah[mi][2] = *(const unsigned*)&sAh[base + 8];
                ah[mi][3] = *(const unsigned*)&sAh[base + 8 * 40 + 8];
                al[mi][0] = *(const unsigned*)&sAl[base];
                al[mi][1] = *(const unsigned*)&sAl[base + 8 * 40];
                al[mi][2] = *(const unsigned*)&sAl[base + 8];
                al[mi][3] = *(const unsigned*)&sAl[base + 8 * 40 + 8];
            }
            #pragma unroll
            for (int ni = 0; ni < 4; ni++) {
                int base = (wn * 32 + ni * 8 + g) * 40 + ks + 2 * t;
                bh[ni][0] = *(const unsigned*)&sWh[base];
                bh[ni][1] = *(const unsigned*)&sWh[base + 8];
                bl[ni][0] = *(const unsigned*)&sWl[base];
                bl[ni][1] = *(const unsigned*)&sWl[base + 8];
            }
            #pragma unroll
            for (int mi = 0; mi < 4; mi++)
                #pragma unroll
                for (int ni = 0; ni < 4; ni++) {
                    mma16816(acc[mi][ni], ah[mi], bh[ni]);
                    mma16816(acc[mi][ni], ah[mi], bl[ni]);
                    mma16816(acc[mi][ni], al[mi], bh[ni]);
                }
        }
        __syncthreads();
    }

    // epilogue
    #pragma unroll
    for (int mi = 0; mi < 4; mi++) {
        #pragma unroll
        for (int ni = 0; ni < 4; ni++) {
            int row = m0 + wm * 64 + mi * 16 + g;
            int col = n0 + wn * 32 + ni * 8 + 2 * t;
            #pragma unroll
            for (int half = 0; half < 2; half++) {
                int r = row + half * 8;
                float vx = acc[mi][ni][2 * half + 0] * scale;
                float vy = acc[mi][ni][2 * half + 1] * scale;
                if (mode == 3) {
                    *(float2*)&Cout[(size_t)r * N + col] = make_float2(vx, vy);
                } else {
                    int b = r / L_, l = r % L_;
                    int h = col / DK_, dk = col % DK_;
                    size_t idx = ((size_t)(b * H_ + h) * L_ + l) * DK_ + dk;
                    if (mode == 2) {
                        *(float2*)&g_V[idx] = make_float2(vx, vy);
                    } else {
                        __nv_bfloat162 hi2, lo2;
                        split2(vx, vy, hi2, lo2);
                        if (mode == 0) {
                            *(__nv_bfloat162*)&g_Qh[idx] = hi2;
                            *(__nv_bfloat162*)&g_Ql[idx] = lo2;
                        } else {
                            *(__nv_bfloat162*)&g_Kh[idx] = hi2;
                            *(__nv_bfloat162*)&g_Kl[idx] = lo2;
                        }
                    }
                }
            }
        }
    }
}

// ---------------------------------------------------------------------------
// Scores per (b,h): S = Q @ K^T (k=64), Q pre-scaled by 1/16, mask applied.
// Same MMA skeleton, K-dim 64 (two 32-chunks).
// ---------------------------------------------------------------------------
__global__ __launch_bounds__(256, 1)
void scores_mma_kernel(const int* __restrict__ mask)
{
    __shared__ __nv_bfloat16 sAh[128 * 40];
    __shared__ __nv_bfloat16 sAl[128 * 40];
    __shared__ __nv_bfloat16 sWh[128 * 40];
    __shared__ __nv_bfloat16 sWl[128 * 40];

    int bh = blockIdx.z;
    int b = bh >> 4;  // H_ = 16
    const __nv_bfloat16* Qh = g_Qh + (size_t)bh * L_ * DK_;
    const __nv_bfloat16* Ql = g_Ql + (size_t)bh * L_ * DK_;
    const __nv_bfloat16* Kh = g_Kh + (size_t)bh * L_ * DK_;
    const __nv_bfloat16* Kl = g_Kl + (size_t)bh * L_ * DK_;
    float* S = g_S + (size_t)bh * L_ * L_;

    int tid = threadIdx.x;
    int warp = tid >> 5, lane = tid & 31;
    int wm = warp >> 2, wn = warp & 3;
    int g = lane >> 2, t = lane & 3;
    int q0 = blockIdx.y * 128;
    int c0 = blockIdx.x * 128;

    float acc[4][4][4] = {};

    for (int k0 = 0; k0 < DK_; k0 += 32) {
        #pragma unroll
        for (int i = 0; i < 2; i++) {
            int f = tid + i * 256;
            int r = f >> 2;
            int c8 = (f & 3) * 8;
            size_t ga = (size_t)(q0 + r) * DK_ + k0 + c8;
            size_t gw = (size_t)(c0 + r) * DK_ + k0 + c8;
            *(float4*)&sAh[r * 40 + c8] = *(const float4*)&Qh[ga];
            *(float4*)&sAl[r * 40 + c8] = *(const float4*)&Ql[ga];
            *(float4*)&sWh[r * 40 + c8] = *(const float4*)&Kh[gw];
            *(float4*)&sWl[r * 40 + c8] = *(const float4*)&Kl[gw];
        }
        __syncthreads();

        #pragma unroll
        for (int ks = 0; ks < 32; ks += 16) {
            unsigned ah[4][4], al[4][4], bh2[4][2], bl2[4][2];
            #pragma unroll
            for (int mi = 0; mi < 4; mi++) {
                int base = (wm * 64 + mi * 16 + g) * 40 + ks + 2 * t;
                ah[mi][0] = *(const unsigned*)&sAh[base];
                ah[mi][1] = *(const unsigned*)&sAh[base + 8 * 40];
                ah[mi][2] = *(const unsigned*)&sAh[base + 8];
                ah[mi][3] = *(const unsigned*)&sAh[base + 8 * 40 + 8];
                al[mi][0] = *(const unsigned*)&sAl[base];
                al[mi][1] = *(const unsigned*)&sAl[base + 8 * 40];
                al[mi][2] = *(const unsigned*)&sAl[base + 8];
                al[mi][3] = *(const unsigned*)&sAl[base + 8 * 40 + 8];
            }
            #pragma unroll
            for (int ni = 0; ni < 4; ni++) {
                int base = (wn * 32 + ni * 8 + g) * 40 + ks + 2 * t;
                bh2[ni][0] = *(const unsigned*)&sWh[base];
                bh2[ni][1] = *(const unsigned*)&sWh[base + 8];
                bl2[ni][0] = *(const unsigned*)&sWl[base];
                bl2[ni][1] = *(const unsigned*)&sWl[base + 8];
            }
            #pragma unroll
            for (int mi = 0; mi < 4; mi++)
                #pragma unroll
                for (int ni = 0; ni < 4; ni++) {
                    mma16816(acc[mi][ni], ah[mi], bh2[ni]);
                    mma16816(acc[mi][ni], ah[mi], bl2[ni]);
                    mma16816(acc[mi][ni], al[mi], bh2[ni]);
                }
        }
        __syncthreads();
    }

    #pragma unroll
    for (int mi = 0; mi < 4; mi++) {
        #pragma unroll
        for (int ni = 0; ni < 4; ni++) {
            int qg = q0 + wm * 64 + mi * 16 + g;
            int kg = c0 + wn * 32 + ni * 8 + 2 * t;
            #pragma unroll
            for (int half = 0; half < 2; half++) {
                int r = qg + half * 8;
                int2 m2 = *(const int2*)&mask[((size_t)b * L_ + r) * L_ + kg];
                float2 v;
                v.x = (m2.x == 0) ? -1e30f : acc[mi][ni][2 * half + 0];
                v.y = (m2.y == 0) ? -1e30f : acc[mi][ni][2 * half + 1];
                *(float2*)&S[(size_t)r * L_ + kg] = v;
            }
        }
    }
}

// ---------------------------------------------------------------------------
// Exact 1.5-entmax per row: bisection on tau, sum relu(z-tau)^2 = 1,
// tau in [zmax-1, zmax]. Row in registers: 256 thr x 8. In-place in g_S.
// ---------------------------------------------------------------------------
__global__ __launch_bounds__(256)
void entmax_kernel()
{
    float* s = g_S + (size_t)blockIdx.x * L_;
    int t = threadIdx.x;

    float z[8];
    #pragma unroll
    for (int j = 0; j < 8; j++) z[j] = s[t + j * 256];

    __shared__ float red[8];
    __shared__ float bcast;

    float m = z[0];
    #pragma unroll
    for (int j = 1; j < 8; j++) m = fmaxf(m, z[j]);
    #pragma unroll
    for (int o = 16; o; o >>= 1) m = fmaxf(m, __shfl_xor_sync(0xffffffffu, m, o));
    if ((t & 31) == 0) red[t >> 5] = m;
    __syncthreads();
    if (t == 0) {
        float mm = red[0];
        #pragma unroll
        for (int w = 1; w < 8; w++) mm = fmaxf(mm, red[w]);
        bcast = mm;
    }
    __syncthreads();
    float zmax = bcast;

    float lo = zmax - 1.0f, hi = zmax;
    for (int it = 0; it < 24; it++) {
        float mid = 0.5f * (lo + hi);
        float ssum = 0.0f;
        #pragma unroll
        for (int j = 0; j < 8; j++) {
            float d = fmaxf(z[j] - mid, 0.0f);
            ssum += d * d;
        }
        #pragma unroll
        for (int o = 16; o; o >>= 1) ssum += __shfl_xor_sync(0xffffffffu, ssum, o);
        if ((t & 31) == 0) red[t >> 5] = ssum;
        __syncthreads();
        if (t == 0) {
            float tot = red[0];
            #pragma unroll
            for (int w = 1; w < 8; w++) tot += red[w];
            bcast = tot;
        }
        __syncthreads();
        if (bcast >= 1.0f) lo = mid; else hi = mid;
    }
    float tau = 0.5f * (lo + hi);

    #pragma unroll
    for (int j = 0; j < 8; j++) {
        float d = fmaxf(z[j] - tau, 0.0f);
        s[t + j * 256] = d * d;
    }
}

// ---------------------------------------------------------------------------
// ctx = P @ V per (b,h), zero-tile skipping (entmax probs very sparse).
// Writes ctx pre-split bf16 into g_inHi/g_inLo ([B,L,D] layout) for O-proj.
// ---------------------------------------------------------------------------
__global__ __launch_bounds__(256)
void av_kernel()
{
    int bh = blockIdx.y;
    int b = bh / H_, h = bh % H_;
    const float* P = g_S + (size_t)bh * L_ * L_;
    const float* V = g_V + (size_t)bh * L_ * DK_;
    int m0 = blockIdx.x * 64;

    __shared__ float Ps[64][36];
    __shared__ float Vs[32][68];
    int tid = threadIdx.x;
    int tx = tid & 15, ty = tid >> 4;
    float acc[4][4] = {};

    for (int k0 = 0; k0 < L_; k0 += 32) {
        int nz = 0;
        #pragma unroll
        for (int i = 0; i < 2; i++) {
            int f = tid + i * 256;
            int pr = f >> 3, pc = (f & 7) * 4;
            float4 pv = *(const float4*)&P[(size_t)(m0 + pr) * L_ + k0 + pc];
            *(float4*)&Ps[pr][pc] = pv;
            nz |= (pv.x != 0.0f) | (pv.y != 0.0f) | (pv.z != 0.0f) | (pv.w != 0.0f);
            int vr = f >> 4, vc = (f & 15) * 4;
            *(float4*)&Vs[vr][vc] = *(const float4*)&V[(size_t)(k0 + vr) * DK_ + vc];
        }
        int any = __syncthreads_or(nz);
        if (any) {
            #pragma unroll
            for (int kk = 0; kk < 32; kk++) {
                float a[4], vv[4];
                #pragma unroll
                for (int i = 0; i < 4; i++) a[i] = Ps[ty * 4 + i][kk];
                #pragma unroll
                for (int j = 0; j < 4; j++) vv[j] = Vs[kk][tx * 4 + j];
                #pragma unroll
                for (int i = 0; i < 4; i++)
                    #pragma unroll
                    for (int j = 0; j < 4; j++)
                        acc[i][j] += a[i] * vv[j];
            }
        }
        __syncthreads();
    }

    #pragma unroll
    for (int i = 0; i < 4; i++) {
        int l = m0 + ty * 4 + i;
        size_t base = ((size_t)(b * L_ + l)) * D_ + h * DK_ + tx * 4;
        __nv_bfloat162 h01, l01, h23, l23;
        split2(acc[i][0], acc[i][1], h01, l01);
        split2(acc[i][2], acc[i][3], h23, l23);
        *(__nv_bfloat162*)&g_inHi[base]     = h01;
        *(__nv_bfloat162*)&g_inHi[base + 2] = h23;
        *(__nv_bfloat162*)&g_inLo[base]     = l01;
        *(__nv_bfloat162*)&g_inLo[base + 2] = l23;
    }
}

// ---------------------------------------------------------------------------
extern "C" void kernel_launch(void* const* d_in, const int* in_sizes, int n_in,
                              void* d_out, int out_size)
{
    const float* q    = (const float*)d_in[0];
    const float* k    = (const float*)d_in[1];
    const float* v    = (const float*)d_in[2];
    const int*   mask = (const int*)  d_in[3];
    const float* w_q  = (const float*)d_in[4];
    const float* w_k  = (const float*)d_in[5];
    const float* w_v  = (const float*)d_in[6];
    const float* w_o  = (const float*)d_in[7];
    float* out = (float*)d_out;

    __nv_bfloat16 *inHi, *inLo, *wHi, *wLo;
    cudaGetSymbolAddress((void**)&inHi, g_inHi);
    cudaGetSymbolAddress((void**)&inLo, g_inLo);
    cudaGetSymbolAddress((void**)&wHi,  g_wHi);
    cudaGetSymbolAddress((void**)&wLo,  g_wLo);

    const int nIn4 = NT_ * D_ / 4;   // 1M float4
    const int nW4  = D_ * D_ / 4;    // 256K float4
    dim3 gProj(D_ / 128, NT_ / 128);        // (8, 32)
    dim3 gScores(L_ / 128, L_ / 128, BH_);  // (16, 16, 32)
    dim3 gAV(L_ / 64, BH_);                 // (32, 32)

    // Q projection (scale folds 1/sqrt(64) * 1/2 entmax = 1/16)
    split_kernel<<<nIn4 / 256, 256>>>(q, inHi, inLo, nIn4);
    split_kernel<<<nW4 / 256, 256>>>(w_q, wHi, wLo, nW4);
    mma_gemm_kernel<<<gProj, 256>>>(inHi, inLo, wHi, wLo, nullptr,
                                    NT_, D_, D_, 1.0f / 16.0f, 0);
    // K projection
    split_kernel<<<nIn4 / 256, 256>>>(k, inHi, inLo, nIn4);
    split_kernel<<<nW4 / 256, 256>>>(w_k, wHi, wLo, nW4);
    mma_gemm_kernel<<<gProj, 256>>>(inHi, inLo, wHi, wLo, nullptr,
                                    NT_, D_, D_, 1.0f, 1);
    // V projection
    split_kernel<<<nIn4 / 256, 256>>>(v, inHi, inLo, nIn4);
    split_kernel<<<nW4 / 256, 256>>>(w_v, wHi, wLo, nW4);
    mma_gemm_kernel<<<gProj, 256>>>(inHi, inLo, wHi, wLo, nullptr,
                                    NT_, D_, D_, 1.0f, 2);

    scores_mma_kernel<<<gScores, 256>>>(mask);
    entmax_kernel<<<BH_ * L_, 256>>>();
    av_kernel<<<gAV, 256>>>();    // writes split ctx into g_inHi/g_inLo

    // Output projection
    split_kernel<<<nW4 / 256, 256>>>(w_o, wHi, wLo, nW4);
    mma_gemm_kernel<<<gProj, 256>>>(inHi, inLo, wHi, wLo, out,
                                    NT_, D_, D_, 1.0f, 3);
}

// round 16
// speedup vs baseline: 1.1633x; 1.1633x over previous
#include <cuda_runtime.h>
#include <cuda_bf16.h>

// Problem constants
constexpr int B_  = 2;
constexpr int L_  = 2048;
constexpr int D_  = 1024;
constexpr int H_  = 16;
constexpr int DK_ = 64;
constexpr int NT_ = B_ * L_;   // 4096 tokens
constexpr int BH_ = B_ * H_;   // 32

// --------------------------- device scratch --------------------------------
__device__ __nv_bfloat16 g_inHi[NT_ * D_];   // input / ctx split (reused)
__device__ __nv_bfloat16 g_inLo[NT_ * D_];
__device__ __nv_bfloat16 g_wHi[D_ * D_];     // weight split (reused per proj)
__device__ __nv_bfloat16 g_wLo[D_ * D_];
__device__ __nv_bfloat16 g_Qh[BH_ * L_ * DK_];   // [bh][l][dk]
__device__ __nv_bfloat16 g_Ql[BH_ * L_ * DK_];
__device__ __nv_bfloat16 g_Kh[BH_ * L_ * DK_];
__device__ __nv_bfloat16 g_Kl[BH_ * L_ * DK_];
__device__ __nv_bfloat16 g_Vth[BH_ * DK_ * L_];  // V transposed: [bh][dk][l]
__device__ __nv_bfloat16 g_Vtl[BH_ * DK_ * L_];

// --------------------------- bf16 split helpers ----------------------------
__device__ __forceinline__ void split2(float x, float y,
                                       __nv_bfloat162& hi, __nv_bfloat162& lo)
{
    hi = __floats2bfloat162_rn(x, y);
    float rx = x - __bfloat162float(hi.x);
    float ry = y - __bfloat162float(hi.y);
    lo = __floats2bfloat162_rn(rx, ry);
}

// Elementwise fp32 -> (hi, lo) bf16 split. n4 = element count / 4.
__global__ __launch_bounds__(256)
void split_kernel(const float* __restrict__ src,
                  __nv_bfloat16* __restrict__ hi,
                  __nv_bfloat16* __restrict__ lo, int n4)
{
    int i = blockIdx.x * 256 + threadIdx.x;
    if (i >= n4) return;
    float4 f = ((const float4*)src)[i];
    __nv_bfloat162 h01, l01, h23, l23;
    split2(f.x, f.y, h01, l01);
    split2(f.z, f.w, h23, l23);
    ((__nv_bfloat162*)hi)[2 * i]     = h01;
    ((__nv_bfloat162*)hi)[2 * i + 1] = h23;
    ((__nv_bfloat162*)lo)[2 * i]     = l01;
    ((__nv_bfloat162*)lo)[2 * i + 1] = l23;
}

// --------------------------- MMA primitive ---------------------------------
__device__ __forceinline__ void mma16816(float* c, const unsigned* a, const unsigned* b)
{
    asm volatile(
        "mma.sync.aligned.m16n8k16.row.col.f32.bf16.bf16.f32 "
        "{%0,%1,%2,%3}, {%4,%5,%6,%7}, {%8,%9}, {%0,%1,%2,%3};\n"
        : "+f"(c[0]), "+f"(c[1]), "+f"(c[2]), "+f"(c[3])
        : "r"(a[0]), "r"(a[1]), "r"(a[2]), "r"(a[3]), "r"(b[0]), "r"(b[1]));
}

// ---------------------------------------------------------------------------
// C = scale * A(MxK) @ W^T, A/W pre-split bf16 (k contiguous).
// Block 128x128, 256 thr (8 warps: wm 0-1 x 64 rows, wn 0-3 x 32 cols).
// 3-term bf16 split accumulation.
// mode 0: scatter hi/lo to g_Qh/g_Ql   (scale folded: 1/16)
// mode 1: scatter hi/lo to g_Kh/g_Kl
// mode 2: scatter hi/lo TRANSPOSED to g_Vth/g_Vtl ([bh][dk][l])
// mode 3: flat fp32 to Cout
// ---------------------------------------------------------------------------
__global__ __launch_bounds__(256, 1)
void mma_gemm_kernel(const __nv_bfloat16* __restrict__ Ah,
                     const __nv_bfloat16* __restrict__ Al,
                     const __nv_bfloat16* __restrict__ Wh,
                     const __nv_bfloat16* __restrict__ Wl,
                     float* __restrict__ Cout,
                     int M, int N, int K, float scale, int mode)
{
    __shared__ __nv_bfloat16 sAh[128 * 40];  // row stride 40 halves: bank-clean
    __shared__ __nv_bfloat16 sAl[128 * 40];
    __shared__ __nv_bfloat16 sWh[128 * 40];
    __shared__ __nv_bfloat16 sWl[128 * 40];

    int tid = threadIdx.x;
    int warp = tid >> 5, lane = tid & 31;
    int wm = warp >> 2, wn = warp & 3;
    int g = lane >> 2, t = lane & 3;
    int m0 = blockIdx.y * 128;
    int n0 = blockIdx.x * 128;

    float acc[4][4][4] = {};

    for (int k0 = 0; k0 < K; k0 += 32) {
        #pragma unroll
        for (int i = 0; i < 2; i++) {
            int f = tid + i * 256;       // 0..511
            int r = f >> 2;              // 0..127
            int c8 = (f & 3) * 8;
            size_t ga = (size_t)(m0 + r) * K + k0 + c8;
            size_t gw = (size_t)(n0 + r) * K + k0 + c8;
            *(float4*)&sAh[r * 40 + c8] = *(const float4*)&Ah[ga];
            *(float4*)&sAl[r * 40 + c8] = *(const float4*)&Al[ga];
            *(float4*)&sWh[r * 40 + c8] = *(const float4*)&Wh[gw];
            *(float4*)&sWl[r * 40 + c8] = *(const float4*)&Wl[gw];
        }
        __syncthreads();

        #pragma unroll
        for (int ks = 0; ks < 32; ks += 16) {
            unsigned ah[4][4], al[4][4], bh[4][2], bl[4][2];
            #pragma unroll
            for (int mi = 0; mi < 4; mi++) {
                int base = (wm * 64 + mi * 16 + g) * 40 + ks + 2 * t;
                ah[mi][0] = *(const unsigned*)&sAh[base];
                ah[mi][1] = *(const unsigned*)&sAh[base + 8 * 40];
                ah[mi][2] = *(const unsigned*)&sAh[base + 8];
                ah[mi][3] = *(const unsigned*)&sAh[base + 8 * 40 + 8];
                al[mi][0] = *(const unsigned*)&sAl[base];
                al[mi][1] = *(const unsigned*)&sAl[base + 8 * 40];
                al[mi][2] = *(const unsigned*)&sAl[base + 8];
                al[mi][3] = *(const unsigned*)&sAl[base + 8 * 40 + 8];
            }
            #pragma unroll
            for (int ni = 0; ni < 4; ni++) {
                int base = (wn * 32 + ni * 8 + g) * 40 + ks + 2 * t;
                bh[ni][0] = *(const unsigned*)&sWh[base];
                bh[ni][1] = *(const unsigned*)&sWh[base + 8];
                bl[ni][0] = *(const unsigned*)&sWl[base];
                bl[ni][1] = *(const unsigned*)&sWl[base + 8];
            }
            #pragma unroll
            for (int mi = 0; mi < 4; mi++)
                #pragma unroll
                for (int ni = 0; ni < 4; ni++) {
                    mma16816(acc[mi][ni], ah[mi], bh[ni]);
                    mma16816(acc[mi][ni], ah[mi], bl[ni]);
                    mma16816(acc[mi][ni], al[mi], bh[ni]);
                }
        }
        __syncthreads();
    }

    // epilogue
    #pragma unroll
    for (int mi = 0; mi < 4; mi++) {
        #pragma unroll
        for (int ni = 0; ni < 4; ni++) {
            int row = m0 + wm * 64 + mi * 16 + g;
            int col = n0 + wn * 32 + ni * 8 + 2 * t;
            #pragma unroll
            for (int half = 0; half < 2; half++) {
                int r = row + half * 8;
                float vx = acc[mi][ni][2 * half + 0] * scale;
                float vy = acc[mi][ni][2 * half + 1] * scale;
                if (mode == 3) {
                    *(float2*)&Cout[(size_t)r * N + col] = make_float2(vx, vy);
                } else {
                    int b = r / L_, l = r % L_;
                    int h = col >> 6, dk = col & 63;
                    __nv_bfloat162 hi2, lo2;
                    split2(vx, vy, hi2, lo2);
                    if (mode == 2) {
                        size_t tb = (((size_t)(b * H_ + h)) * DK_ + dk) * L_ + l;
                        g_Vth[tb]      = hi2.x;
                        g_Vth[tb + L_] = hi2.y;
                        g_Vtl[tb]      = lo2.x;
                        g_Vtl[tb + L_] = lo2.y;
                    } else {
                        size_t idx = ((size_t)(b * H_ + h) * L_ + l) * DK_ + dk;
                        if (mode == 0) {
                            *(__nv_bfloat162*)&g_Qh[idx] = hi2;
                            *(__nv_bfloat162*)&g_Ql[idx] = lo2;
                        } else {
                            *(__nv_bfloat162*)&g_Kh[idx] = hi2;
                            *(__nv_bfloat162*)&g_Kl[idx] = lo2;
                        }
                    }
                }
            }
        }
    }
}

// ---------------------------------------------------------------------------
// Fused attention: per CTA = (bh, 16 q-rows).
//  Phase 1: scores S = Q@K^T (3-term bf16 MMA) into registers z[128]/thread
//           (16 x 2048 stripe), mask applied.
//  Phase 2: per-row exact 1.5-entmax threshold via Newton on
//           g(tau) = sum relu(z - tau)^2 - 1  (convex, C1, from-left monotone).
//  Phase 3: ctx = P@V with P = relu(z-tau)^2 packed to hi/lo bf16 A-frags,
//           V^T staged per chunk, zero chunks skipped. ctx written hi/lo
//           split to g_inHi/g_inLo for the O-projection.
// ---------------------------------------------------------------------------
__global__ __launch_bounds__(256, 1)
void fused_attn_kernel(const int* __restrict__ mask)
{
    __shared__ __nv_bfloat16 sBh[128 * 72];  // union: K chunk (scores) / V^T chunk (AV)
    __shared__ __nv_bfloat16 sBl[128 * 72];
    __shared__ __nv_bfloat16 sQh[16 * 72];
    __shared__ __nv_bfloat16 sQl[16 * 72];
    __shared__ float sOut[16 * 68];
    __shared__ float sRed[8 * 16 * 2];       // [warp][row][s1,s2]
    __shared__ float sTau[16];
    __shared__ float sZmax[16];

    const int tid = threadIdx.x;
    const int w = tid >> 5, lane = tid & 31;
    const int g = lane >> 2, t = lane & 3;
    const int bh = blockIdx.y;
    const int b = bh >> 4, h = bh & 15;      // H_ = 16
    const int q0 = blockIdx.x * 16;

    const __nv_bfloat16* Qh = g_Qh + (size_t)bh * L_ * DK_;
    const __nv_bfloat16* Ql = g_Ql + (size_t)bh * L_ * DK_;
    const __nv_bfloat16* Kh = g_Kh + (size_t)bh * L_ * DK_;
    const __nv_bfloat16* Kl = g_Kl + (size_t)bh * L_ * DK_;
    const __nv_bfloat16* Vth = g_Vth + (size_t)bh * DK_ * L_;
    const __nv_bfloat16* Vtl = g_Vtl + (size_t)bh * DK_ * L_;

    for (int i = tid; i < 16 * 68; i += 256) sOut[i] = 0.0f;

    // stage Q tile (16 x 64, hi/lo)
    if (tid < 128) {
        int r = tid >> 3, c8 = (tid & 7) * 8;
        *(float4*)&sQh[r * 72 + c8] = *(const float4*)&Qh[(size_t)(q0 + r) * DK_ + c8];
        *(float4*)&sQl[r * 72 + c8] = *(const float4*)&Ql[(size_t)(q0 + r) * DK_ + c8];
    }
    __syncthreads();

    unsigned aQh[4][4], aQl[4][4];
    #pragma unroll
    for (int ks = 0; ks < 4; ks++) {
        int base = g * 72 + ks * 16 + 2 * t;
        aQh[ks][0] = *(const unsigned*)&sQh[base];
        aQh[ks][1] = *(const unsigned*)&sQh[base + 8 * 72];
        aQh[ks][2] = *(const unsigned*)&sQh[base + 8];
        aQh[ks][3] = *(const unsigned*)&sQh[base + 8 * 72 + 8];
        aQl[ks][0] = *(const unsigned*)&sQl[base];
        aQl[ks][1] = *(const unsigned*)&sQl[base + 8 * 72];
        aQl[ks][2] = *(const unsigned*)&sQl[base + 8];
        aQl[ks][3] = *(const unsigned*)&sQl[base + 8 * 72 + 8];
    }

    float z[128];   // this thread's scores: z[c*8 + j*4 + rh*2 + e]

    // ---------------- Phase 1: scores ----------------
    #pragma unroll
    for (int c = 0; c < 16; c++) {
        #pragma unroll
        for (int i = 0; i < 4; i++) {
            int f = tid + i * 256;
            int r = f >> 3, c8 = (f & 7) * 8;
            *(float4*)&sBh[r * 72 + c8] = *(const float4*)&Kh[(size_t)(c * 128 + r) * DK_ + c8];
            *(float4*)&sBl[r * 72 + c8] = *(const float4*)&Kl[(size_t)(c * 128 + r) * DK_ + c8];
        }
        __syncthreads();

        #pragma unroll
        for (int j = 0; j < 2; j++) {
            float acc[4] = {0.f, 0.f, 0.f, 0.f};
            int nrow = w * 16 + j * 8 + g;
            #pragma unroll
            for (int ks = 0; ks < 4; ks++) {
                unsigned bKh[2], bKl2[2];
                int base = nrow * 72 + ks * 16 + 2 * t;
                bKh[0]  = *(const unsigned*)&sBh[base];
                bKh[1]  = *(const unsigned*)&sBh[base + 8];
                bKl2[0] = *(const unsigned*)&sBl[base];
                bKl2[1] = *(const unsigned*)&sBl[base + 8];
                mma16816(acc, aQh[ks], bKh);
                mma16816(acc, aQh[ks], bKl2);
                mma16816(acc, aQl[ks], bKh);
            }
            int colb = c * 128 + w * 16 + j * 8 + 2 * t;
            #pragma unroll
            for (int rh = 0; rh < 2; rh++) {
                int row = q0 + g + rh * 8;
                int2 m2 = *(const int2*)&mask[((size_t)b * L_ + row) * L_ + colb];
                z[c * 8 + j * 4 + rh * 2 + 0] = m2.x ? acc[rh * 2 + 0] : -1e30f;
                z[c * 8 + j * 4 + rh * 2 + 1] = m2.y ? acc[rh * 2 + 1] : -1e30f;
            }
        }
        __syncthreads();
    }

    // ---------------- Phase 2: row max + Newton for tau ----------------
    float ma = -1e38f, mb = -1e38f;
    #pragma unroll
    for (int i = 0; i < 128; i += 4) {
        ma = fmaxf(ma, fmaxf(z[i], z[i + 1]));
        mb = fmaxf(mb, fmaxf(z[i + 2], z[i + 3]));
    }
    ma = fmaxf(ma, __shfl_xor_sync(0xffffffffu, ma, 1));
    ma = fmaxf(ma, __shfl_xor_sync(0xffffffffu, ma, 2));
    mb = fmaxf(mb, __shfl_xor_sync(0xffffffffu, mb, 1));
    mb = fmaxf(mb, __shfl_xor_sync(0xffffffffu, mb, 2));
    if (t == 0) {
        sRed[(w * 16 + g) * 2]     = ma;
        sRed[(w * 16 + g + 8) * 2] = mb;
    }
    __syncthreads();
    if (tid < 16) {
        float mm = sRed[tid * 2];
        #pragma unroll
        for (int ww = 1; ww < 8; ww++) mm = fmaxf(mm, sRed[(ww * 16 + tid) * 2]);
        sZmax[tid] = mm;
        sTau[tid] = mm - 1.0f;
    }
    __syncthreads();
    float tauA = sTau[g], tauB = sTau[g + 8];

    for (int it = 0; it < 12; it++) {
        float s1a = 0.f, s2a = 0.f, s1b = 0.f, s2b = 0.f;
        #pragma unroll
        for (int i = 0; i < 128; i += 4) {
            float d0 = fmaxf(z[i]     - tauA, 0.f);
            float d1 = fmaxf(z[i + 1] - tauA, 0.f);
            float d2 = fmaxf(z[i + 2] - tauB, 0.f);
            float d3 = fmaxf(z[i + 3] - tauB, 0.f);
            s1a += d0 + d1;  s2a = fmaf(d0, d0, fmaf(d1, d1, s2a));
            s1b += d2 + d3;  s2b = fmaf(d2, d2, fmaf(d3, d3, s2b));
        }
        s1a += __shfl_xor_sync(0xffffffffu, s1a, 1);
        s1a += __shfl_xor_sync(0xffffffffu, s1a, 2);
        s2a += __shfl_xor_sync(0xffffffffu, s2a, 1);
        s2a += __shfl_xor_sync(0xffffffffu, s2a, 2);
        s1b += __shfl_xor_sync(0xffffffffu, s1b, 1);
        s1b += __shfl_xor_sync(0xffffffffu, s1b, 2);
        s2b += __shfl_xor_sync(0xffffffffu, s2b, 1);
        s2b += __shfl_xor_sync(0xffffffffu, s2b, 2);
        if (t == 0) {
            sRed[(w * 16 + g) * 2]         = s1a;
            sRed[(w * 16 + g) * 2 + 1]     = s2a;
            sRed[(w * 16 + g + 8) * 2]     = s1b;
            sRed[(w * 16 + g + 8) * 2 + 1] = s2b;
        }
        __syncthreads();
        if (tid < 16) {
            float S1 = 0.f, S2 = 0.f;
            #pragma unroll
            for (int ww = 0; ww < 8; ww++) {
                S1 += sRed[(ww * 16 + tid) * 2];
                S2 += sRed[(ww * 16 + tid) * 2 + 1];
            }
            float tau = sTau[tid];
            if (S1 > 0.f) tau += (S2 - 1.0f) / (2.0f * S1);
            // tau* <= zmax - 1/sqrt(2048); clamp only guards fp rounding
            sTau[tid] = fminf(tau, sZmax[tid] - 0.022f);
        }
        __syncthreads();
        tauA = sTau[g]; tauB = sTau[g + 8];
    }

    // ---------------- Phase 3: ctx = P @ V ----------------
    float accO[8][4] = {};
    #pragma unroll
    for (int c = 0; c < 16; c++) {
        float p[8];
        #pragma unroll
        for (int j = 0; j < 2; j++) {
            float d0 = fmaxf(z[c * 8 + j * 4 + 0] - tauA, 0.f);
            float d1 = fmaxf(z[c * 8 + j * 4 + 1] - tauA, 0.f);
            float d2 = fmaxf(z[c * 8 + j * 4 + 2] - tauB, 0.f);
            float d3 = fmaxf(z[c * 8 + j * 4 + 3] - tauB, 0.f);
            p[j * 4 + 0] = d0 * d0;
            p[j * 4 + 1] = d1 * d1;
            p[j * 4 + 2] = d2 * d2;
            p[j * 4 + 3] = d3 * d3;
        }
        float psum = p[0] + p[1] + p[2] + p[3] + p[4] + p[5] + p[6] + p[7];
        int anyL = (psum > 0.f);
        int ba = __syncthreads_or(anyL);
        if (!ba) continue;

        #pragma unroll
        for (int i = 0; i < 4; i++) {
            int f = tid + i * 256;
            int dk = f >> 4, c8 = (f & 15) * 8;
            *(float4*)&sBh[dk * 136 + c8] = *(const float4*)&Vth[(size_t)dk * L_ + c * 128 + c8];
            *(float4*)&sBl[dk * 136 + c8] = *(const float4*)&Vtl[(size_t)dk * L_ + c * 128 + c8];
        }
        __syncthreads();

        if (__ballot_sync(0xffffffffu, anyL)) {
            unsigned aPh[4], aPl[4];
            #pragma unroll
            for (int q = 0; q < 4; q++) {
                float x = p[q * 2], y = p[q * 2 + 1];
                __nv_bfloat162 hi2, lo2;
                split2(x, y, hi2, lo2);
                aPh[q] = *reinterpret_cast<unsigned*>(&hi2);
                aPl[q] = *reinterpret_cast<unsigned*>(&lo2);
            }
            #pragma unroll
            for (int nt = 0; nt < 8; nt++) {
                unsigned bV[2], bVl2[2];
                int base = (nt * 8 + g) * 136 + w * 16 + 2 * t;
                bV[0]   = *(const unsigned*)&sBh[base];
                bV[1]   = *(const unsigned*)&sBh[base + 8];
                bVl2[0] = *(const unsigned*)&sBl[base];
                bVl2[1] = *(const unsigned*)&sBl[base + 8];
                mma16816(accO[nt], aPh, bV);
                mma16816(accO[nt], aPh, bVl2);
                mma16816(accO[nt], aPl, bV);
            }
        }
        __syncthreads();
    }

    // sequential cross-warp accumulation of out partials
    for (int ws = 0; ws < 8; ws++) {
        if (w == ws) {
            #pragma unroll
            for (int nt = 0; nt < 8; nt++) {
                sOut[g * 68 + nt * 8 + 2 * t]           += accO[nt][0];
                sOut[g * 68 + nt * 8 + 2 * t + 1]       += accO[nt][1];
                sOut[(g + 8) * 68 + nt * 8 + 2 * t]     += accO[nt][2];
                sOut[(g + 8) * 68 + nt * 8 + 2 * t + 1] += accO[nt][3];
            }
        }
        __syncthreads();
    }

    // epilogue: split ctx to hi/lo bf16 for O-projection
    for (int i = tid; i < 512; i += 256) {   // 512 bf16x2 pairs = 16x64
        int r = i >> 5, dk2 = (i & 31) * 2;
        float vx = sOut[r * 68 + dk2], vy = sOut[r * 68 + dk2 + 1];
        __nv_bfloat162 hi2, lo2;
        split2(vx, vy, hi2, lo2);
        size_t base = ((size_t)(b * L_ + q0 + r)) * D_ + h * DK_ + dk2;
        *(__nv_bfloat162*)&g_inHi[base] = hi2;
        *(__nv_bfloat162*)&g_inLo[base] = lo2;
    }
}

// ---------------------------------------------------------------------------
extern "C" void kernel_launch(void* const* d_in, const int* in_sizes, int n_in,
                              void* d_out, int out_size)
{
    const float* q    = (const float*)d_in[0];
    const float* k    = (const float*)d_in[1];
    const float* v    = (const float*)d_in[2];
    const int*   mask = (const int*)  d_in[3];
    const float* w_q  = (const float*)d_in[4];
    const float* w_k  = (const float*)d_in[5];
    const float* w_v  = (const float*)d_in[6];
    const float* w_o  = (const float*)d_in[7];
    float* out = (float*)d_out;

    __nv_bfloat16 *inHi, *inLo, *wHi, *wLo;
    cudaGetSymbolAddress((void**)&inHi, g_inHi);
    cudaGetSymbolAddress((void**)&inLo, g_inLo);
    cudaGetSymbolAddress((void**)&wHi,  g_wHi);
    cudaGetSymbolAddress((void**)&wLo,  g_wLo);

    const int nIn4 = NT_ * D_ / 4;
    const int nW4  = D_ * D_ / 4;
    dim3 gProj(D_ / 128, NT_ / 128);        // (8, 32)
    dim3 gFused(L_ / 16, BH_);              // (128, 32)

    // Q projection (scale folds 1/sqrt(d_k) * 1/2 entmax = 1/16)
    split_kernel<<<nIn4 / 256, 256>>>(q, inHi, inLo, nIn4);
    split_kernel<<<nW4 / 256, 256>>>(w_q, wHi, wLo, nW4);
    mma_gemm_kernel<<<gProj, 256>>>(inHi, inLo, wHi, wLo, nullptr,
                                    NT_, D_, D_, 1.0f / 16.0f, 0);
    // K projection
    split_kernel<<<nIn4 / 256, 256>>>(k, inHi, inLo, nIn4);
    split_kernel<<<nW4 / 256, 256>>>(w_k, wHi, wLo, nW4);
    mma_gemm_kernel<<<gProj, 256>>>(inHi, inLo, wHi, wLo, nullptr,
                                    NT_, D_, D_, 1.0f, 1);
    // V projection (writes V^T hi/lo bf16)
    split_kernel<<<nIn4 / 256, 256>>>(v, inHi, inLo, nIn4);
    split_kernel<<<nW4 / 256, 256>>>(w_v, wHi, wLo, nW4);
    mma_gemm_kernel<<<gProj, 256>>>(inHi, inLo, wHi, wLo, nullptr,
                                    NT_, D_, D_, 1.0f, 2);

    // fused scores + entmax + AV (writes split ctx into g_inHi/g_inLo)
    fused_attn_kernel<<<gFused, 256>>>(mask);

    // Output projection
    split_kernel<<<nW4 / 256, 256>>>(w_o, wHi, wLo, nW4);
    mma_gemm_kernel<<<gProj, 256>>>(inHi, inLo, wHi, wLo, out,
                                    NT_, D_, D_, 1.0f, 3);
}